// round 5
// baseline (speedup 1.0000x reference)
#include <cuda_runtime.h>

#define TT      65536
#define HID     128
#define G3      384
#define INS     96
#define LIN     32
#define CHUNK   16
#define NCHUNK  (TT / CHUNK)   // 4096
#define NPROD   147
#define NBLK    (NPROD + 1)    // 148

// 96 MB scratch for precomputed input gates, + chunk-ready flags
__device__ float g_ig[TT * G3];
__device__ int   g_flag[NCHUNK];

// ---------- f32x2 helpers ----------
static __device__ __forceinline__ unsigned long long pk2(float a, float b) {
    unsigned long long r;
    asm("mov.b64 %0, {%1,%2};" : "=l"(r) : "f"(a), "f"(b));
    return r;
}
static __device__ __forceinline__ void fma2(unsigned long long& d,
                                            unsigned long long a,
                                            unsigned long long b) {
    asm("fma.rn.f32x2 %0, %1, %2, %0;" : "+l"(d) : "l"(a), "l"(b));
}
static __device__ __forceinline__ unsigned long long add2(unsigned long long a,
                                                          unsigned long long b) {
    unsigned long long r;
    asm("add.rn.f32x2 %0, %1, %2;" : "=l"(r) : "l"(a), "l"(b));
    return r;
}
static __device__ __forceinline__ float lo_hi_sum(unsigned long long v) {
    float lo, hi;
    asm("mov.b64 {%0,%1}, %2;" : "=f"(lo), "=f"(hi) : "l"(v));
    return lo + hi;
}

// ---------- fast transcendentals (MUFU-based, ~1e-6 rel err) ----------
static __device__ __forceinline__ float fex2(float x) {
    float r; asm("ex2.approx.f32 %0, %1;" : "=f"(r) : "f"(x)); return r;
}
static __device__ __forceinline__ float frcp(float x) {
    float r; asm("rcp.approx.f32 %0, %1;" : "=f"(r) : "f"(x)); return r;
}
static __device__ __forceinline__ float sigmoid_f(float x) {
    // 1 / (1 + exp(-x)) ; exp(-x) = 2^(-x*log2e)
    return frcp(1.0f + fex2(-1.4426950408889634f * x));
}
static __device__ __forceinline__ float tanh_f(float x) {
    float ax = fabsf(x);
    float e  = fex2(-2.885390081777927f * ax);   // exp(-2*ax)
    float t  = (1.0f - e) * frcp(1.0f + e);
    return copysignf(t, x);
}

// ---------- clear flags each launch (graph-replay safe) ----------
__global__ void gru_clear_flags() {
    int i = blockIdx.x * blockDim.x + threadIdx.x;
    if (i < NCHUNK) g_flag[i] = 0;
}

// ---------- fused kernel: block 0 = sequential scan, blocks 1..147 = igates GEMM ----------
__global__ __launch_bounds__(G3, 1)
void gru_fused(const float* __restrict__ x_gru,   // (T, 96)
               const float* __restrict__ x_lin,   // (T, 32)
               const float* __restrict__ h_init,  // (128,)
               const float* __restrict__ w_ih,    // (384, 96)
               const float* __restrict__ w_hh,    // (384, 128)
               const float* __restrict__ b_ih,    // (384,)
               const float* __restrict__ b_nv,    // (128,)
               const float* __restrict__ lbias_p, // (1,)
               float* __restrict__ out)           // (T, 1)
{
    __shared__ __align__(16) float smem[1664];
    const int tid = threadIdx.x;

    if (blockIdx.x != 0) {
        // ===================== PRODUCER: igates = x_gru @ w_ih.T + b_ih =====================
        const int b   = blockIdx.x - 1;   // 0..146
        const int row = tid;              // 0..383
        float wreg[INS];
        {
            const float* wp = w_ih + row * INS;
            #pragma unroll
            for (int k = 0; k < INS; k++) wreg[k] = wp[k];
        }
        const float bih = b_ih[row];

        for (int c = b; c < NCHUNK; c += NPROD) {
            const int t0 = c * CHUNK;
            __syncthreads();  // smem reuse guard across chunks
            // load CHUNK rows of x (coalesced), transposed into smem: smem[k*17 + tt]
            for (int i = tid; i < CHUNK * INS; i += G3) {
                int ttl = i / INS, k = i % INS;
                smem[k * 17 + ttl] = x_gru[(t0 + ttl) * INS + k];
            }
            __syncthreads();

            float acc[CHUNK];
            #pragma unroll
            for (int ttl = 0; ttl < CHUNK; ttl++) acc[ttl] = bih;
            #pragma unroll
            for (int k = 0; k < INS; k++) {
                const float w = wreg[k];
                #pragma unroll
                for (int ttl = 0; ttl < CHUNK; ttl++)
                    acc[ttl] = fmaf(w, smem[k * 17 + ttl], acc[ttl]);
            }
            #pragma unroll
            for (int ttl = 0; ttl < CHUNK; ttl++)
                g_ig[(t0 + ttl) * G3 + row] = acc[ttl];

            __syncthreads();  // all threads' stores issued before the release
            if (tid == 0) {
                __threadfence();
                atomicExch(&g_flag[c], 1);
            }
        }
        return;
    }

    // ===================== SCAN (single persistent CTA) =====================
    float* sh_h  = smem;        // [128] hidden state
    float* s_z   = smem + 128;  // [128] update gate
    float* s_np  = smem + 256;  // [128] hn + b_n
    float* s_ign = smem + 384;  // [128] i_n

    // thread tid owns w_hh row tid, packed as 64 f32x2 values in registers
    unsigned long long w[64];
    {
        const float2* wr = reinterpret_cast<const float2*>(w_hh + tid * HID);
        #pragma unroll
        for (int i = 0; i < 64; i++) { float2 v = wr[i]; w[i] = pk2(v.x, v.y); }
    }

    if (tid < HID) sh_h[tid] = h_init[tid];
    float h_reg = (tid < HID) ? h_init[tid] : 0.0f;
    const float bn    = (tid >= 256) ? b_nv[tid - 256] : 0.0f;
    const float lbias = lbias_p[0];

    // wait for chunk 0 (covers steps 0 and 1 prefetch)
    {
        int f;
        const int* fp = &g_flag[0];
        do { asm volatile("ld.acquire.gpu.global.b32 %0, [%1];" : "=r"(f) : "l"(fp)); } while (f == 0);
    }
    __syncthreads();

    float ig0 = g_ig[0 * G3 + tid];
    float ig1 = g_ig[1 * G3 + tid];
    float xl0 = 0.0f, xl1 = 0.0f;
    if (tid < LIN) { xl0 = x_lin[tid]; xl1 = x_lin[LIN + tid]; }

    for (int t = 0; t < TT; t++) {
        // ---- phase A: hgate[tid] = dot(w_row, h) via f32x2, h broadcast from smem ----
        unsigned long long a0 = 0ull, a1 = 0ull, a2 = 0ull, a3 = 0ull;
        const ulonglong2* h4 = reinterpret_cast<const ulonglong2*>(sh_h);
        #pragma unroll
        for (int i = 0; i < 32; i += 2) {
            ulonglong2 p = h4[i];
            ulonglong2 q = h4[i + 1];
            fma2(a0, w[2 * i],     p.x);
            fma2(a1, w[2 * i + 1], p.y);
            fma2(a2, w[2 * i + 2], q.x);
            fma2(a3, w[2 * i + 3], q.y);
        }
        const float g  = lo_hi_sum(add2(add2(a0, a1), add2(a2, a3)));
        const float ig = ig0;
        ig0 = ig1;

        // prefetch igates for t+2 (flag-gated at chunk boundaries)
        const int tp = t + 2;
        if (tp < TT) {
            if ((tp & (CHUNK - 1)) == 0) {
                const int c = tp >> 4;
                int f;
                const int* fp = &g_flag[c];
                do { asm volatile("ld.acquire.gpu.global.b32 %0, [%1];" : "=r"(f) : "l"(fp)); } while (f == 0);
            }
            ig1 = g_ig[tp * G3 + tid];
        }

        // per-row post-processing (warp-uniform branches: warps 0-3 / 4-7 / 8-11)
        float r = 0.0f;
        if (tid < 128) {
            r = sigmoid_f(g + ig);          // reset gate, stays in register
        } else if (tid < 256) {
            s_z[tid - 128] = sigmoid_f(g + ig);
        } else {
            s_np[tid - 256]  = g + bn;      // hn + b_n (igate kept separate!)
            s_ign[tid - 256] = ig;          // i_n
        }
        __syncthreads();  // bar1: hgate-derived values published; all reads of sh_h done

        // ---- phase B: gate combine (threads 0..127) ----
        if (tid < 128) {
            const float n  = tanh_f(s_ign[tid] + r * s_np[tid]);
            const float z  = s_z[tid];
            const float hn = fmaf(z, h_reg - n, n);   // n + z*(h - n)
            h_reg = hn;
            sh_h[tid] = hn;
        }
        __syncthreads();  // bar2: new h visible to all

        // ---- output: warp 0, overlaps next step's matvec of other warps ----
        if (tid < LIN) {
            float p = h_reg * xl0;          // h_reg = h_new[tid] for tid < 32
            xl0 = xl1;
            xl1 = (tp < TT) ? x_lin[tp * LIN + tid] : 0.0f;
            p += __shfl_xor_sync(0xffffffffu, p, 16);
            p += __shfl_xor_sync(0xffffffffu, p, 8);
            p += __shfl_xor_sync(0xffffffffu, p, 4);
            p += __shfl_xor_sync(0xffffffffu, p, 2);
            p += __shfl_xor_sync(0xffffffffu, p, 1);
            if (tid == 0) out[t] = p + lbias;
        }
    }
}

extern "C" void kernel_launch(void* const* d_in, const int* in_sizes, int n_in,
                              void* d_out, int out_size) {
    const float* x_gru = (const float*)d_in[0];  // (65536, 96)
    const float* x_lin = (const float*)d_in[1];  // (65536, 32)
    const float* h0    = (const float*)d_in[2];  // (128,)
    const float* w_ih  = (const float*)d_in[3];  // (384, 96)
    const float* w_hh  = (const float*)d_in[4];  // (384, 128)
    const float* b_ih  = (const float*)d_in[5];  // (384,)
    const float* b_n   = (const float*)d_in[6];  // (128,)
    const float* lb    = (const float*)d_in[7];  // (1,)
    float* out = (float*)d_out;                  // (65536, 1)

    gru_clear_flags<<<(NCHUNK + 255) / 256, 256>>>();
    gru_fused<<<NBLK, G3>>>(x_gru, x_lin, h0, w_ih, w_hh, b_ih, b_n, lb, out);
}

// round 6
// speedup vs baseline: 1.1332x; 1.1332x over previous
#include <cuda_runtime.h>

#define TT      65536
#define HID     128
#define G3      384
#define INS     96
#define LIN     32
#define CHUNK   16
#define NCHUNK  (TT / CHUNK)   // 4096
#define NPROD   147
#define NBLK    (NPROD + 1)    // 148
#define NT      512

// 96 MB scratch for precomputed input gates, + chunk-ready flags
__device__ float g_ig[TT * G3];
__device__ int   g_flag[NCHUNK];

// ---------- f32x2 helpers ----------
static __device__ __forceinline__ unsigned long long pk2(float a, float b) {
    unsigned long long r;
    asm("mov.b64 %0, {%1,%2};" : "=l"(r) : "f"(a), "f"(b));
    return r;
}
static __device__ __forceinline__ void fma2(unsigned long long& d,
                                            unsigned long long a,
                                            unsigned long long b) {
    asm("fma.rn.f32x2 %0, %1, %2, %0;" : "+l"(d) : "l"(a), "l"(b));
}
static __device__ __forceinline__ float lo_hi_sum(unsigned long long v) {
    float lo, hi;
    asm("mov.b64 {%0,%1}, %2;" : "=f"(lo), "=f"(hi) : "l"(v));
    return lo + hi;
}

// ---------- fast transcendentals (MUFU-based, ~1e-6 rel err) ----------
static __device__ __forceinline__ float fex2(float x) {
    float r; asm("ex2.approx.f32 %0, %1;" : "=f"(r) : "f"(x)); return r;
}
static __device__ __forceinline__ float frcp(float x) {
    float r; asm("rcp.approx.f32 %0, %1;" : "=f"(r) : "f"(x)); return r;
}
static __device__ __forceinline__ float sigmoid_f(float x) {
    return frcp(1.0f + fex2(-1.4426950408889634f * x));
}
static __device__ __forceinline__ float tanh_f(float x) {
    float ax = fabsf(x);
    float e  = fex2(-2.885390081777927f * ax);   // exp(-2*ax) via ex2
    float t  = (1.0f - e) * frcp(1.0f + e);
    return copysignf(t, x);
}

static __device__ __forceinline__ void wait_flag(const int* fp) {
    int f;
    do { asm volatile("ld.acquire.gpu.global.b32 %0, [%1];" : "=r"(f) : "l"(fp)); } while (f == 0);
}

// ---------- clear flags each launch (graph-replay safe) ----------
__global__ void gru_clear_flags() {
    int i = blockIdx.x * blockDim.x + threadIdx.x;
    if (i < NCHUNK) g_flag[i] = 0;
}

// ---------- fused kernel: block 0 = sequential scan, blocks 1..147 = igates GEMM ----------
__global__ __launch_bounds__(NT, 1)
void gru_fused(const float* __restrict__ x_gru,   // (T, 96)
               const float* __restrict__ x_lin,   // (T, 32)
               const float* __restrict__ h_init,  // (128,)
               const float* __restrict__ w_ih,    // (384, 96)
               const float* __restrict__ w_hh,    // (384, 128)
               const float* __restrict__ b_ih,    // (384,)
               const float* __restrict__ b_nv,    // (128,)
               const float* __restrict__ lbias_p, // (1,)
               float* __restrict__ out)           // (T, 1)
{
    __shared__ __align__(16) float smem[1700];
    const int tid = threadIdx.x;

    if (blockIdx.x != 0) {
        // ============ PRODUCER: igates = x_gru @ w_ih.T + b_ih, chunks of 16 ============
        const int b = blockIdx.x - 1;   // 0..146
        for (int c = b; c < NCHUNK; c += NPROD) {
            const int t0 = c * CHUNK;
            __syncthreads();  // smem reuse guard across chunks
            for (int i = tid; i < CHUNK * INS; i += NT) {
                int ttl = i / INS, k = i % INS;
                smem[k * 17 + ttl] = x_gru[(size_t)(t0 + ttl) * INS + k];
            }
            __syncthreads();
            if (tid < G3) {
                const float* wp = w_ih + tid * INS;
                const float bih = b_ih[tid];
                float acc[CHUNK];
                #pragma unroll
                for (int ttl = 0; ttl < CHUNK; ttl++) acc[ttl] = bih;
                #pragma unroll 4
                for (int k = 0; k < INS; k++) {
                    const float w = wp[k];
                    #pragma unroll
                    for (int ttl = 0; ttl < CHUNK; ttl++)
                        acc[ttl] = fmaf(w, smem[k * 17 + ttl], acc[ttl]);
                }
                #pragma unroll
                for (int ttl = 0; ttl < CHUNK; ttl++)
                    g_ig[(size_t)(t0 + ttl) * G3 + tid] = acc[ttl];
            }
            __syncthreads();  // all stores issued before the release
            if (tid == 0) {
                __threadfence();
                atomicExch(&g_flag[c], 1);
            }
        }
        return;
    }

    // ===================== SCAN (single persistent CTA, 512 threads) =====================
    // warp w, lane l: row = w*8 + l/4 (0..127), kq = l&3 selects a 32-wide K slice.
    const int wid  = tid >> 5;
    const int lane = tid & 31;
    const int row  = wid * 8 + (lane >> 2);
    const int kq   = lane & 3;

    // padded h buffers: element e stored at (e>>5)*36 + (e&31)  -> conflict-free quad reads
    float* shA = smem;          // 144 floats
    float* shB = smem + 144;    // 144 floats
    float* soA = smem + 288;    // 4 output partials (even steps)
    float* soB = smem + 296;    // 4 output partials (odd steps)

    // weights: 3 gates x 32 K-values = 48 f32x2 regs
    unsigned long long wr_[16], wz_[16], wn_[16];
    {
        const float2* p0 = (const float2*)(w_hh + (size_t)(row      ) * HID) + kq * 16;
        const float2* p1 = (const float2*)(w_hh + (size_t)(row + 128) * HID) + kq * 16;
        const float2* p2 = (const float2*)(w_hh + (size_t)(row + 256) * HID) + kq * 16;
        #pragma unroll
        for (int j = 0; j < 16; j++) { float2 v = p0[j]; wr_[j] = pk2(v.x, v.y); }
        #pragma unroll
        for (int j = 0; j < 16; j++) { float2 v = p1[j]; wz_[j] = pk2(v.x, v.y); }
        #pragma unroll
        for (int j = 0; j < 16; j++) { float2 v = p2[j]; wn_[j] = pk2(v.x, v.y); }
    }
    const float bn    = b_nv[row];
    const float lbias = lbias_p[0];
    float h_reg = h_init[row];
    if (kq == 0) shA[(row >> 5) * 36 + (row & 31)] = h_reg;

    wait_flag(&g_flag[0]);
    __syncthreads();

    float igr0, igz0, ign0, igr1, igz1, ign1;
    {
        const float* gp = g_ig + row;
        igr0 = gp[0];      igz0 = gp[128];      ign0 = gp[256];
        igr1 = gp[G3];     igz1 = gp[G3 + 128]; ign1 = gp[G3 + 256];
    }
    float xl0 = 0.0f, xl1 = 0.0f;
    if (wid < 4) { xl0 = x_lin[row]; xl1 = x_lin[LIN + row]; }  // rows 0..31

    auto step = [&](int t, const float* hrd, float* hwr, float* so_w, const float* so_r) {
        // ---- matvec: 3 gate slices over this thread's 32 h values ----
        unsigned long long ar = 0ull, az = 0ull, an2 = 0ull;
        const ulonglong2* h2 = (const ulonglong2*)(hrd + kq * 36);
        #pragma unroll
        for (int j = 0; j < 8; j++) {
            ulonglong2 v = h2[j];
            fma2(ar,  wr_[2 * j],     v.x); fma2(ar,  wr_[2 * j + 1], v.y);
            fma2(az,  wz_[2 * j],     v.x); fma2(az,  wz_[2 * j + 1], v.y);
            fma2(an2, wn_[2 * j],     v.x); fma2(an2, wn_[2 * j + 1], v.y);
        }
        float gr = lo_hi_sum(ar), gz = lo_hi_sum(az), gn = lo_hi_sum(an2);
        gr += __shfl_xor_sync(0xffffffffu, gr, 1);
        gr += __shfl_xor_sync(0xffffffffu, gr, 2);
        gz += __shfl_xor_sync(0xffffffffu, gz, 1);
        gz += __shfl_xor_sync(0xffffffffu, gz, 2);
        gn += __shfl_xor_sync(0xffffffffu, gn, 1);
        gn += __shfl_xor_sync(0xffffffffu, gn, 2);

        // ---- gates (all 4 quad lanes redundantly; no cross-warp hand-off) ----
        const float r    = sigmoid_f(gr + igr0);
        const float z    = sigmoid_f(gz + igz0);
        const float n    = tanh_f(ign0 + r * (gn + bn));
        const float hnew = fmaf(z, h_reg - n, n);
        h_reg = hnew;
        if (kq == 0) hwr[(row >> 5) * 36 + (row & 31)] = hnew;

        // ---- shift + prefetch igates (t+2) ----
        igr0 = igr1; igz0 = igz1; ign0 = ign1;
        const int tp = t + 2;
        if (tp < TT) {
            const float* gp = g_ig + (size_t)tp * G3 + row;
            igr1 = gp[0]; igz1 = gp[128]; ign1 = gp[256];
        }

        // ---- output partial: rows 0..31 live in warps 0..3 ----
        if (wid < 4) {
            float p = (kq == 0) ? hnew * xl0 : 0.0f;
            xl0 = xl1;
            xl1 = (tp < TT) ? x_lin[(size_t)tp * LIN + row] : 0.0f;
            p += __shfl_xor_sync(0xffffffffu, p, 4);
            p += __shfl_xor_sync(0xffffffffu, p, 8);
            p += __shfl_xor_sync(0xffffffffu, p, 16);
            if (lane == 0) so_w[wid] = p;
        }
        // ---- finalize previous step's output (one idle-duty thread) ----
        if (tid == NT - 2 && t > 0)
            out[t - 1] = so_r[0] + so_r[1] + so_r[2] + so_r[3] + lbias;

        __syncthreads();  // single barrier per step (h double-buffered)
    };

    for (int c = 0; c < NCHUNK; c++) {
        if (c + 1 < NCHUNK) wait_flag(&g_flag[c + 1]);
        const int t0 = c * CHUNK;
        #pragma unroll 1
        for (int s = 0; s < CHUNK; s += 2) {
            step(t0 + s,     shA, shB, soA, soB);
            step(t0 + s + 1, shB, shA, soB, soA);
        }
    }
    if (tid == NT - 2)
        out[TT - 1] = soB[0] + soB[1] + soB[2] + soB[3] + lbias;
}

extern "C" void kernel_launch(void* const* d_in, const int* in_sizes, int n_in,
                              void* d_out, int out_size) {
    const float* x_gru = (const float*)d_in[0];  // (65536, 96)
    const float* x_lin = (const float*)d_in[1];  // (65536, 32)
    const float* h0    = (const float*)d_in[2];  // (128,)
    const float* w_ih  = (const float*)d_in[3];  // (384, 96)
    const float* w_hh  = (const float*)d_in[4];  // (384, 128)
    const float* b_ih  = (const float*)d_in[5];  // (384,)
    const float* b_n   = (const float*)d_in[6];  // (128,)
    const float* lb    = (const float*)d_in[7];  // (1,)
    float* out = (float*)d_out;                  // (65536, 1)

    gru_clear_flags<<<(NCHUNK + 255) / 256, 256>>>();
    gru_fused<<<NBLK, NT>>>(x_gru, x_lin, h0, w_ih, w_hh, b_ih, b_n, lb, out);
}